// round 2
// baseline (speedup 1.0000x reference)
#include <cuda_runtime.h>
#include <cuda_bf16.h>

// ---------------------------------------------------------------------------
// CFConv: f = x @ W_in ; wf = w_ij * f[idx_j] ; conv = segment_sum(wf, seg_i)
//         out = conv @ W_out + b_out
// Shapes: x[20000,128], w_ij[640000,128], seg_i/idx_j[640000] (seg_i sorted),
//         W_in/W_out[128,128], b_out[128]. All fp32.
//
// Capture-safety: kernel_launch performs ONLY kernel launches. Scratch lives
// in __device__ globals referenced directly from device code (no
// cudaGetSymbolAddress). All shared memory is static and <= 48 KB (no
// cudaFuncSetAttribute).
// ---------------------------------------------------------------------------

#define NFM 128
#define N_ATOMS_MAX 20000

__device__ float g_f[N_ATOMS_MAX * NFM];     // f = x @ W_in
__device__ float g_conv[N_ATOMS_MAX * NFM];  // segment-sum accumulator

// ---------------------------------------------------------------------------
// GEMM: C[n,128] = A[n,128] @ W[128,128] (+ bias).
// mode 0: A = A_ext,  C = g_f,   and zero g_conv rows alongside the store.
// mode 1: A = g_conv, C = C_ext, add bias.
// Block: 256 threads, 64 rows/block. K split into two 64-wide phases so the
// static smem footprint is exactly 48 KB (Ws 64x128 + Xs 64x64).
// Per-thread micro-tile: 8 rows x 4 cols.
// ---------------------------------------------------------------------------
__global__ void __launch_bounds__(256, 2) gemm128_kernel(
    const float* __restrict__ A_ext, const float* __restrict__ W,
    const float* __restrict__ bias, float* __restrict__ C_ext,
    int mode, int n)
{
    __shared__ float Ws[64 * NFM];  // 32 KB: K-slice of W (64 rows x 128 cols)
    __shared__ float Xs[64 * 64];   // 16 KB: 64 rows x 64-K-slice of A

    const float* A = (mode == 1) ? g_conv : A_ext;
    float*       C = (mode == 1) ? C_ext  : g_f;

    const int tid  = threadIdx.x;
    const int row0 = blockIdx.x * 64;

    const int lane = tid & 31;
    const int wrp  = tid >> 5;
    const int c    = lane * 4;   // output cols c..c+3
    const int r0   = wrp * 8;    // local rows r0..r0+7

    float acc[8][4];
#pragma unroll
    for (int i = 0; i < 8; i++)
        acc[i][0] = acc[i][1] = acc[i][2] = acc[i][3] = 0.f;

#pragma unroll
    for (int kb = 0; kb < NFM; kb += 64) {
        // Load W rows kb..kb+63 (all 128 cols): 2048 float4, 8 per thread
        {
            const float4* W4  = (const float4*)(W + (size_t)kb * NFM);
            float4*       Ws4 = (float4*)Ws;
#pragma unroll
            for (int t = 0; t < 8; t++) Ws4[tid + t * 256] = W4[tid + t * 256];
        }
        // Load A tile rows row0..row0+63, cols kb..kb+63: 1024 float4, 4/thread
        {
            const float4* A4  = (const float4*)A;
            float4*       Xs4 = (float4*)Xs;
#pragma unroll
            for (int t = 0; t < 4; t++) {
                int slot = tid + t * 256;        // 0..1023
                int r = slot >> 4, c4 = slot & 15;
                float4 v = make_float4(0.f, 0.f, 0.f, 0.f);
                if (row0 + r < n)
                    v = A4[(size_t)(row0 + r) * 32 + (kb >> 2) + c4];
                Xs4[slot] = v;
            }
        }
        __syncthreads();

#pragma unroll 8
        for (int k = 0; k < 64; k++) {
            float4 b = *(const float4*)&Ws[k * NFM + c];
#pragma unroll
            for (int i = 0; i < 8; i++) {
                float a = Xs[(r0 + i) * 64 + k];
                acc[i][0] = fmaf(a, b.x, acc[i][0]);
                acc[i][1] = fmaf(a, b.y, acc[i][1]);
                acc[i][2] = fmaf(a, b.z, acc[i][2]);
                acc[i][3] = fmaf(a, b.w, acc[i][3]);
            }
        }
        __syncthreads();
    }

    float4 bb = make_float4(0.f, 0.f, 0.f, 0.f);
    if (mode == 1) bb = *(const float4*)&bias[c];

#pragma unroll
    for (int i = 0; i < 8; i++) {
        int r = row0 + r0 + i;
        if (r < n) {
            float4 v = make_float4(acc[i][0] + bb.x, acc[i][1] + bb.y,
                                   acc[i][2] + bb.z, acc[i][3] + bb.w);
            *(float4*)&C[(size_t)r * NFM + c] = v;
            if (mode == 0) {
                *(float4*)&g_conv[(size_t)r * NFM + c] =
                    make_float4(0.f, 0.f, 0.f, 0.f);
            }
        }
    }
}

// ---------------------------------------------------------------------------
// Edge kernel: each warp owns a contiguous chunk of EPW edges (seg_i sorted).
// Lane l handles channels 4l..4l+3 (float4). Register accumulation per
// segment run; atomicAdd flush only at segment boundaries / chunk ends.
// Unrolled x4 so 8 16B loads/thread are in flight (MLP for DRAM latency).
// ---------------------------------------------------------------------------
#define EPW 128

__device__ __forceinline__ void flush_seg(int seg, int c, float4& acc)
{
    atomicAdd(&g_conv[(size_t)seg * NFM + c + 0], acc.x);
    atomicAdd(&g_conv[(size_t)seg * NFM + c + 1], acc.y);
    atomicAdd(&g_conv[(size_t)seg * NFM + c + 2], acc.z);
    atomicAdd(&g_conv[(size_t)seg * NFM + c + 3], acc.w);
    acc = make_float4(0.f, 0.f, 0.f, 0.f);
}

__global__ void __launch_bounds__(256) edge_kernel(
    const float* __restrict__ w_ij, const int* __restrict__ seg_i,
    const int* __restrict__ idx_j, int n_edges)
{
    const int gw   = (blockIdx.x * blockDim.x + threadIdx.x) >> 5;
    const int lane = threadIdx.x & 31;
    long e0 = (long)gw * EPW;
    if (e0 >= n_edges) return;
    long e1 = e0 + EPW;
    if (e1 > n_edges) e1 = n_edges;

    const int c = lane * 4;
    float4 acc  = make_float4(0.f, 0.f, 0.f, 0.f);
    int cur     = seg_i[e0];

    long e = e0;
    for (; e + 4 <= e1; e += 4) {
        int s[4], j[4];
#pragma unroll
        for (int u = 0; u < 4; u++) {
            s[u] = seg_i[e + u];
            j[u] = idx_j[e + u];
        }
        float4 w[4], fj[4];
#pragma unroll
        for (int u = 0; u < 4; u++) {
            w[u]  = *(const float4*)&w_ij[(size_t)(e + u) * NFM + c];
            fj[u] = *(const float4*)&g_f[(size_t)j[u] * NFM + c];
        }
#pragma unroll
        for (int u = 0; u < 4; u++) {
            if (s[u] != cur) { flush_seg(cur, c, acc); cur = s[u]; }
            acc.x = fmaf(w[u].x, fj[u].x, acc.x);
            acc.y = fmaf(w[u].y, fj[u].y, acc.y);
            acc.z = fmaf(w[u].z, fj[u].z, acc.z);
            acc.w = fmaf(w[u].w, fj[u].w, acc.w);
        }
    }
    for (; e < e1; e++) {  // tail (640000 % (32*128/32)==0, kept for safety)
        int s = seg_i[e];
        int j = idx_j[e];
        if (s != cur) { flush_seg(cur, c, acc); cur = s; }
        float4 w  = *(const float4*)&w_ij[(size_t)e * NFM + c];
        float4 fj = *(const float4*)&g_f[(size_t)j * NFM + c];
        acc.x = fmaf(w.x, fj.x, acc.x);
        acc.y = fmaf(w.y, fj.y, acc.y);
        acc.z = fmaf(w.z, fj.z, acc.z);
        acc.w = fmaf(w.w, fj.w, acc.w);
    }
    flush_seg(cur, c, acc);
}

// ---------------------------------------------------------------------------
// Launch. Inputs (metadata order): x, w_ij, seg_i, idx_j, [seg_i_sum?],
// W_in, W_out, b_out. Robust to whether the scalar appears as an input.
// ---------------------------------------------------------------------------
extern "C" void kernel_launch(void* const* d_in, const int* in_sizes, int n_in,
                              void* d_out, int out_size)
{
    const float* x     = (const float*)d_in[0];
    const float* w_ij  = (const float*)d_in[1];
    const int*   seg_i = (const int*)d_in[2];
    const int*   idx_j = (const int*)d_in[3];

    int base = 4;
    if (base < n_in && in_sizes[base] == 1) base = 5;
    const float* W_in  = (const float*)d_in[base + 0];
    const float* W_out = (const float*)d_in[base + 1];
    const float* b_out = (const float*)d_in[base + 2];

    const int n_atoms = in_sizes[0] / NFM;
    const int n_edges = in_sizes[2];

    const int gblocks = (n_atoms + 63) / 64;

    // f = x @ W_in ; zero g_conv alongside
    gemm128_kernel<<<gblocks, 256>>>(x, W_in, nullptr, nullptr, 0, n_atoms);

    // g_conv += segment_sum(w_ij * g_f[idx_j])
    const int warps   = (n_edges + EPW - 1) / EPW;
    const int eblocks = (warps * 32 + 255) / 256;
    edge_kernel<<<eblocks, 256>>>(w_ij, seg_i, idx_j, n_edges);

    // out = g_conv @ W_out + b_out
    gemm128_kernel<<<gblocks, 256>>>(nullptr, W_out, b_out, (float*)d_out,
                                     1, n_atoms);
}